// round 13
// baseline (speedup 1.0000x reference)
#include <cuda_runtime.h>
#include <cuda_fp16.h>
#include <math.h>
#include <stdint.h>

#define Bsz 64
#define Hd  1024
#define Ed  1024
#define Vv  32000
#define Ll  2
#define Tt  64
#define START_TOK 1

#define BK 32
#define XPAD 34
#define VT 128                        // rows per MMA tile
#define NBLK_SCORE (Vv / VT)          // 250
#define KC 64                        // fp16 K elems per chunk (128B rows)
#define NCH 16                        // score: 1024/64
#define NCH_L 4                       // lstm slice: 256/64
#define NSLICE_L 8                    // lstm K-split
#define A_PART 16384                  // 128 rows * 128B
#define B_PART 8192                   // 64 rows * 128B
#define A_REGION (2 * A_PART)         // 32768 (2 fp16 parts)
#define B_REGION (2 * B_PART)         // 16384
#define STAGE_BYTES (A_REGION + B_REGION)  // 49152
#define N_STAGES 2
#define DYN_BYTES (N_STAGES * STAGE_BYTES + 1024)   // 99328 -> 2 CTAs/SM

typedef unsigned long long ull;

// ---------------- persistent device state ----------------
__device__ float  g_cbuf[Ll][Bsz][Hd];       // cell state
__device__ float  g_hfp[Ll][Bsz][Hd];        // h fp32 (o2emb input)
__device__ __half g_hs0[Ll][Bsz][Hd];        // h fp16 split hi
__device__ __half g_hs1[Ll][Bsz][Hd];        // h fp16 split lo
__device__ int    g_xt[Bsz];
__device__ float  g_pval[Bsz][NBLK_SCORE];
__device__ int    g_pidx[Bsz][NBLK_SCORE];
__device__ float  g_gpart[NSLICE_L][Bsz][4 * Hd];  // [k-slice][batch][gate-row n]
__device__ float  g_opart[2][Bsz][Ed];
__device__ int    g_cnt;

// fp16x2 splits (one-time)
__device__ __half g_w0[(size_t)Vv * Ed];     // score_w hi
__device__ __half g_w1[(size_t)Vv * Ed];     // score_w lo
__device__ __half g_e0[(size_t)Vv * Ed];     // emb hi
__device__ __half g_e1[(size_t)Vv * Ed];     // emb lo
__device__ __half g_lw0[Ll * 2 * 4 * Hd * Hd];  // [layer][ih/hh][4096][1024] hi
__device__ __half g_lw1[Ll * 2 * 4 * Hd * Hd];  // lo
// per-step splits
__device__ __half g_h0[Bsz * Ed];            // hid hi
__device__ __half g_h1[Bsz * Ed];            // hid lo

// ---------------- helpers ----------------
__device__ __forceinline__ void ffma2(ull &acc, ull a, ull b) {
    asm("fma.rn.f32x2 %0, %1, %2, %0;" : "+l"(acc) : "l"(a), "l"(b));
}
__device__ __forceinline__ float fsum2(ull v) {
    return __uint_as_float((unsigned)v) + __uint_as_float((unsigned)(v >> 32));
}
__device__ __forceinline__ float sigmoidf_(float x) { return 1.0f / (1.0f + expf(-x)); }

__device__ __forceinline__ uint32_t smem_u32(const void* p) {
    uint32_t a;
    asm("{ .reg .u64 t; cvta.to.shared.u64 t, %1; cvt.u32.u64 %0, t; }" : "=r"(a) : "l"(p));
    return a;
}
__device__ __forceinline__ void cpa16(uint32_t dst, const void* src) {
    asm volatile("cp.async.cg.shared.global [%0], [%1], 16;" :: "r"(dst), "l"(src) : "memory");
}
__device__ __forceinline__ void cpa_commit() {
    asm volatile("cp.async.commit_group;" ::: "memory");
}
template <int N> __device__ __forceinline__ void cpa_wait() {
    asm volatile("cp.async.wait_group %0;" :: "n"(N) : "memory");
}
__device__ __forceinline__ void ldsm_x4(uint32_t* r, uint32_t addr) {
    asm volatile("ldmatrix.sync.aligned.m8n8.x4.shared.b16 {%0,%1,%2,%3}, [%4];"
                 : "=r"(r[0]), "=r"(r[1]), "=r"(r[2]), "=r"(r[3]) : "r"(addr));
}
__device__ __forceinline__ void mma_f16(float* d, const uint32_t* a, uint32_t b0, uint32_t b1) {
    asm volatile(
        "mma.sync.aligned.m16n8k16.row.col.f32.f16.f16.f32 "
        "{%0,%1,%2,%3}, {%4,%5,%6,%7}, {%8,%9}, {%0,%1,%2,%3};"
        : "+f"(d[0]), "+f"(d[1]), "+f"(d[2]), "+f"(d[3])
        : "r"(a[0]), "r"(a[1]), "r"(a[2]), "r"(a[3]), "r"(b0), "r"(b1));
}
__device__ __forceinline__ uint32_t swz(uint32_t off) { return off ^ ((off >> 3) & 0x70); }

// ---------------- init ----------------
__global__ void init_kernel() {
    int idx = blockIdx.x * blockDim.x + threadIdx.x;
    if (idx < Ll * Bsz * Hd) {
        (&g_cbuf[0][0][0])[idx] = 0.0f;
        (&g_hs0[0][0][0])[idx] = __float2half_rn(0.0f);
        (&g_hs1[0][0][0])[idx] = __float2half_rn(0.0f);
    }
    if (idx < Bsz) g_xt[idx] = START_TOK;
    if (idx == 0) g_cnt = 0;
}

// ---------------- one-time fp16x2 splits ----------------
__global__ __launch_bounds__(256) void split_w_kernel(const float* __restrict__ sw,
                                                      const float* __restrict__ emb) {
    const size_t n = (size_t)Vv * Ed;
    for (size_t i = blockIdx.x * 256ull + threadIdx.x; i < n; i += (size_t)gridDim.x * 256ull) {
        float w = sw[i];
        __half a = __float2half_rn(w);
        g_w0[i] = a;
        g_w1[i] = __float2half_rn(w - __half2float(a));
        float e = emb[i];
        __half c = __float2half_rn(e);
        g_e0[i] = c;
        g_e1[i] = __float2half_rn(e - __half2float(c));
    }
}
__global__ __launch_bounds__(256) void split_lstm_kernel(const float* __restrict__ w_ih,
                                                         const float* __restrict__ w_hh) {
    const size_t n = (size_t)Ll * 2 * 4 * Hd * Hd;
    const size_t per = (size_t)4 * Hd * Hd;
    for (size_t i = blockIdx.x * 256ull + threadIdx.x; i < n; i += (size_t)gridDim.x * 256ull) {
        size_t mat = i / per;
        size_t off = i % per;
        size_t layer = mat >> 1;
        float w = (mat & 1) ? w_hh[layer * per + off] : w_ih[layer * per + off];
        __half a = __float2half_rn(w);
        g_lw0[i] = a;
        g_lw1[i] = __float2half_rn(w - __half2float(a));
    }
}

// ---------------- LSTM partial GEMM via mma.sync fp16x2 ----------------
// grid = (32 gate-row tiles, 8 k-slices), 256 threads.
// Slice s: matrix = (s>=4 ? hh : ih), k window = (s&3)*256. 2-stage pipeline, 2 CTAs/SM.
__global__ __launch_bounds__(256, 2) void lstm_mma_kernel(int layer)
{
    extern __shared__ char dynsm[];
    const int tid  = threadIdx.x;
    const int wid  = tid >> 5;
    const int lane = tid & 31;
    const int n0   = blockIdx.x * VT;
    const int slice = blockIdx.y;
    const int koff = (slice & 3) * 256;
    const int m    = (slice >= 4) ? 1 : 0;

    const uint32_t dbase = (smem_u32(dynsm) + 1023u) & ~1023u;

    const __half* abase0 = g_lw0 + ((size_t)(layer * 2 + m) * 4 * Hd + n0) * Hd + koff;
    const __half* abase1 = g_lw1 + ((size_t)(layer * 2 + m) * 4 * Hd + n0) * Hd + koff;

    auto bsrc = [&](int p, int r) -> const __half* {
        if (layer == 0) {
            if (slice < 4) return (p ? g_e1 : g_e0) + (size_t)g_xt[r] * Ed + koff;
            return &(p ? g_hs1 : g_hs0)[0][r][koff];
        } else {
            if (slice < 4) return &(p ? g_hs1 : g_hs0)[0][r][koff];
            return &(p ? g_hs1 : g_hs0)[1][r][koff];
        }
    };

    auto load_chunk = [&](int kc, int stg) {
        const uint32_t sbase = dbase + stg * STAGE_BYTES;
#pragma unroll
        for (int i = 0; i < 12; i++) {
            int seg = tid + 256 * i;
            const __half* src;
            uint32_t dst;
            if (seg < 2048) {
                int p = seg >> 10, rem = seg & 1023;
                int r = rem >> 3, cb = rem & 7;
                src = (p ? abase1 : abase0) + (size_t)r * Hd + kc * KC + cb * 8;
                dst = sbase + p * A_PART + swz((uint32_t)(r * 128 + cb * 16));
            } else {
                int s2 = seg - 2048;
                int p = s2 >> 9, rem = s2 & 511;
                int r = rem >> 3, cb = rem & 7;
                src = bsrc(p, r) + kc * KC + cb * 8;
                dst = sbase + A_REGION + p * B_PART + swz((uint32_t)(r * 128 + cb * 16));
            }
            cpa16(dst, src);
        }
        cpa_commit();
    };

    float acc[8][4];
#pragma unroll
    for (int j = 0; j < 8; j++)
#pragma unroll
        for (int q = 0; q < 4; q++) acc[j][q] = 0.0f;

    load_chunk(0, 0);
    if (NCH_L > 1) load_chunk(1, 1);

    const int arow = 16 * wid + (lane & 15);
    const int asel = (lane >> 4) & 1;
    const int brow = ((lane & 16) ? 8 : 0) + (lane & 7);
    const int bsel = (lane >> 3) & 1;

    for (int c = 0; c < NCH_L; c++) {
        if (c + 1 < NCH_L) cpa_wait<1>(); else cpa_wait<0>();
        __syncthreads();

        const uint32_t sbase = dbase + (c & 1) * STAGE_BYTES;
        const uint32_t bb = sbase + A_REGION;
#pragma unroll
        for (int kk = 0; kk < 4; kk++) {
            const uint32_t aoff = swz((uint32_t)(arow * 128 + (kk * 2 + asel) * 16));
            uint32_t a0[4], a1[4];
            ldsm_x4(a0, sbase + 0 * A_PART + aoff);
            ldsm_x4(a1, sbase + 1 * A_PART + aoff);
#pragma unroll
            for (int jp = 0; jp < 4; jp++) {
                const uint32_t boff = swz((uint32_t)((jp * 16 + brow) * 128 + (kk * 2 + bsel) * 16));
                uint32_t b[4];
                ldsm_x4(b, bb + 0 * B_PART + boff);       // h0: (w0,h0),(w1,h0)
                mma_f16(acc[2 * jp + 0], a0, b[0], b[1]);
                mma_f16(acc[2 * jp + 1], a0, b[2], b[3]);
                mma_f16(acc[2 * jp + 0], a1, b[0], b[1]);
                mma_f16(acc[2 * jp + 1], a1, b[2], b[3]);
                ldsm_x4(b, bb + 1 * B_PART + boff);       // h1: (w0,h1)
                mma_f16(acc[2 * jp + 0], a0, b[0], b[1]);
                mma_f16(acc[2 * jp + 1], a0, b[2], b[3]);
            }
        }
        __syncthreads();
        if (c + 2 < NCH_L) load_chunk(c + 2, c & 1);
    }

    // epilogue: smem transpose -> coalesced partial writes
    float* red = (float*)(dynsm + (dbase - smem_u32(dynsm)));   // [128][65]
    const int r1 = 16 * wid + (lane >> 2);
    const int r2 = r1 + 8;
#pragma unroll
    for (int j = 0; j < 8; j++) {
        int cc = j * 8 + (lane & 3) * 2;
        red[r1 * 65 + cc + 0] = acc[j][0];
        red[r1 * 65 + cc + 1] = acc[j][1];
        red[r2 * 65 + cc + 0] = acc[j][2];
        red[r2 * 65 + cc + 1] = acc[j][3];
    }
    __syncthreads();
    {
        const int b  = tid >> 2;
        const int v0 = (tid & 3) * 32;
#pragma unroll 8
        for (int i = 0; i < 32; i++)
            g_gpart[slice][b][n0 + v0 + i] = red[(v0 + i) * 65 + b];
    }
}

// ---------------- LSTM cell update: reduce partials + biases, update c/h, split h ----------------
__global__ __launch_bounds__(256) void lstm_cell_kernel(
    const float* __restrict__ b_ih_all, const float* __restrict__ b_hh_all, int layer)
{
    const int idx = blockIdx.x * 256 + threadIdx.x;   // 65536
    const int j   = idx & (Hd - 1);
    const int row = idx >> 10;

    float gi = b_ih_all[layer * 4 * Hd + 0 * Hd + j] + b_hh_all[layer * 4 * Hd + 0 * Hd + j];
    float gf = b_ih_all[layer * 4 * Hd + 1 * Hd + j] + b_hh_all[layer * 4 * Hd + 1 * Hd + j];
    float gg = b_ih_all[layer * 4 * Hd + 2 * Hd + j] + b_hh_all[layer * 4 * Hd + 2 * Hd + j];
    float go = b_ih_all[layer * 4 * Hd + 3 * Hd + j] + b_hh_all[layer * 4 * Hd + 3 * Hd + j];
#pragma unroll
    for (int s = 0; s < NSLICE_L; s++) {
        gi += g_gpart[s][row][0 * Hd + j];
        gf += g_gpart[s][row][1 * Hd + j];
        gg += g_gpart[s][row][2 * Hd + j];
        go += g_gpart[s][row][3 * Hd + j];
    }
    float cold = g_cbuf[layer][row][j];
    float cnew = sigmoidf_(gf) * cold + sigmoidf_(gi) * tanhf(gg);
    float hnew = sigmoidf_(go) * tanhf(cnew);
    g_cbuf[layer][row][j] = cnew;
    g_hfp[layer][row][j]  = hnew;
    __half h0 = __float2half_rn(hnew);
    g_hs0[layer][row][j] = h0;
    g_hs1[layer][row][j] = __float2half_rn(hnew - __half2float(h0));
}

// ---------------- o2emb partial GEMM (scalar FFMA2, K-split x2) ----------------
__global__ __launch_bounds__(128) void o2emb_part_kernel(const float* __restrict__ o2w)
{
    __shared__ float xs[Bsz][XPAD];
    __shared__ float ws[8][XPAD];

    const int tid   = threadIdx.x;
    const int n0    = blockIdx.x * 8;
    const int slice = blockIdx.y;
    const int koff  = slice * 512;
    const int cg    = tid & 7;
    const int rg    = tid >> 3;
    const float* xsrc = &g_hfp[Ll - 1][0][0];

    ull acc[4];
#pragma unroll
    for (int i = 0; i < 4; i++) acc[i] = 0ULL;

    float4 px[4], pw;
    {
#pragma unroll
        for (int i = 0; i < 4; i++) {
            int item = tid + 128 * i;
            int r = item >> 3, c4 = item & 7;
            px[i] = *(const float4*)&xsrc[r * Hd + koff + 4 * c4];
        }
        if (tid < 64) {
            int c = tid >> 3, c4 = tid & 7;
            pw = *(const float4*)&o2w[(size_t)(n0 + c) * Hd + koff + 4 * c4];
        }
    }

    const int NCHU = 512 / BK;   // 16
    for (int chunk = 0; chunk < NCHU; chunk++) {
#pragma unroll
        for (int i = 0; i < 4; i++) {
            int item = tid + 128 * i;
            int r = item >> 3, c4 = item & 7;
            xs[r][4 * c4 + 0] = px[i].x; xs[r][4 * c4 + 1] = px[i].y;
            xs[r][4 * c4 + 2] = px[i].z; xs[r][4 * c4 + 3] = px[i].w;
        }
        if (tid < 64) {
            int c = tid >> 3, c4 = tid & 7;
            ws[c][4 * c4 + 0] = pw.x; ws[c][4 * c4 + 1] = pw.y;
            ws[c][4 * c4 + 2] = pw.z; ws[c][4 * c4 + 3] = pw.w;
        }
        __syncthreads();

        if (chunk + 1 < NCHU) {
            int k0 = koff + (chunk + 1) * BK;
#pragma unroll
            for (int i = 0; i < 4; i++) {
                int item = tid + 128 * i;
                int r = item >> 3, c4 = item & 7;
                px[i] = *(const float4*)&xsrc[r * Hd + k0 + 4 * c4];
            }
            if (tid < 64) {
                int c = tid >> 3, c4 = tid & 7;
                pw = *(const float4*)&o2w[(size_t)(n0 + c) * Hd + k0 + 4 * c4];
            }
        }

#pragma unroll
        for (int k2 = 0; k2 < BK / 2; k2++) {
            ull wv = *(const ull*)&ws[cg][2 * k2];
#pragma unroll
            for (int i = 0; i < 4; i++) {
                ull xv = *(const ull*)&xs[4 * rg + i][2 * k2];
                ffma2(acc[i], xv, wv);
            }
        }
        __syncthreads();
    }

    const int n = n0 + cg;
#pragma unroll
    for (int i = 0; i < 4; i++)
        g_opart[slice][4 * rg + i][n] = fsum2(acc[i]);
}

// ---------------- o2emb combine: bias + relu -> fp16x2 split ----------------
__global__ __launch_bounds__(256) void o2emb_comb_kernel(const float* __restrict__ o2b) {
    const int idx = blockIdx.x * 256 + threadIdx.x;   // 65536
    const int n   = idx & (Ed - 1);
    const int row = idx >> 10;
    float v = g_opart[0][row][n] + g_opart[1][row][n] + o2b[n];
    v = v > 0.0f ? v : 0.0f;
    __half p0 = __float2half_rn(v);
    g_h0[idx] = p0;
    g_h1[idx] = __float2half_rn(v - __half2float(p0));
}

// ---------------- score via mma.sync fp16x2 + fused final argmax ----------------
__global__ __launch_bounds__(256, 2) void score_mma_kernel(
    const float* __restrict__ score_b, float* __restrict__ out, int t, int out_size)
{
    extern __shared__ char dynsm[];
    __shared__ bool amLast;

    const int tid  = threadIdx.x;
    const int wid  = tid >> 5;
    const int lane = tid & 31;
    const int n0   = blockIdx.x * VT;

    const uint32_t dbase = (smem_u32(dynsm) + 1023u) & ~1023u;

    auto load_chunk = [&](int kc, int stg) {
        const uint32_t sbase = dbase + stg * STAGE_BYTES;
#pragma unroll
        for (int i = 0; i < 12; i++) {
            int seg = tid + 256 * i;
            const __half* src;
            uint32_t dst;
            if (seg < 2048) {
                int p = seg >> 10, rem = seg & 1023;
                int r = rem >> 3, cb = rem & 7;
                src = (p ? g_w1 : g_w0) + (((size_t)(n0 + r)) << 10) + kc * KC + cb * 8;
                dst = sbase + p * A_PART + swz((uint32_t)(r * 128 + cb * 16));
            } else {
                int s2 = seg - 2048;
                int p = s2 >> 9, rem = s2 & 511;
                int r = rem >> 3, cb = rem & 7;
                src = (p ? g_h1 : g_h0) + (r << 10) + kc * KC + cb * 8;
                dst = sbase + A_REGION + p * B_PART + swz((uint32_t)(r * 128 + cb * 16));
            }
            cpa16(dst, src);
        }
        cpa_commit();
    };

    float acc[8][4];
#pragma unroll
    for (int j = 0; j < 8; j++)
#pragma unroll
        for (int q = 0; q < 4; q++) acc[j][q] = 0.0f;

    load_chunk(0, 0);
    load_chunk(1, 1);

    const int arow = 16 * wid + (lane & 15);
    const int asel = (lane >> 4) & 1;
    const int brow = ((lane & 16) ? 8 : 0) + (lane & 7);
    const int bsel = (lane >> 3) & 1;

    for (int c = 0; c < NCH; c++) {
        if (c + 1 < NCH) cpa_wait<1>(); else cpa_wait<0>();
        __syncthreads();

        const uint32_t sbase = dbase + (c & 1) * STAGE_BYTES;
        const uint32_t bb = sbase + A_REGION;
#pragma unroll
        for (int kk = 0; kk < 4; kk++) {
            const uint32_t aoff = swz((uint32_t)(arow * 128 + (kk * 2 + asel) * 16));
            uint32_t a0[4], a1[4];
            ldsm_x4(a0, sbase + 0 * A_PART + aoff);
            ldsm_x4(a1, sbase + 1 * A_PART + aoff);
#pragma unroll
            for (int jp = 0; jp < 4; jp++) {
                const uint32_t boff = swz((uint32_t)((jp * 16 + brow) * 128 + (kk * 2 + bsel) * 16));
                uint32_t b[4];
                ldsm_x4(b, bb + 0 * B_PART + boff);
                mma_f16(acc[2 * jp + 0], a0, b[0], b[1]);
                mma_f16(acc[2 * jp + 1], a0, b[2], b[3]);
                mma_f16(acc[2 * jp + 0], a1, b[0], b[1]);
                mma_f16(acc[2 * jp + 1], a1, b[2], b[3]);
                ldsm_x4(b, bb + 1 * B_PART + boff);
                mma_f16(acc[2 * jp + 0], a0, b[0], b[1]);
                mma_f16(acc[2 * jp + 1], a0, b[2], b[3]);
            }
        }
        __syncthreads();
        if (c + 2 < NCH) load_chunk(c + 2, c & 1);
    }

    // ---------------- epilogue ----------------
    float* red = (float*)(dynsm + (dbase - smem_u32(dynsm)));  // [128][65]

    const int r1 = 16 * wid + (lane >> 2);
    const int r2 = r1 + 8;
    const float bias1 = score_b[n0 + r1];
    const float bias2 = score_b[n0 + r2];
#pragma unroll
    for (int j = 0; j < 8; j++) {
        int cc = j * 8 + (lane & 3) * 2;
        red[r1 * 65 + cc + 0] = acc[j][0] + bias1;
        red[r1 * 65 + cc + 1] = acc[j][1] + bias1;
        red[r2 * 65 + cc + 0] = acc[j][2] + bias2;
        red[r2 * 65 + cc + 1] = acc[j][3] + bias2;
    }
    __syncthreads();

    {
        const int b  = tid >> 2;
        const int v0 = (tid & 3) * 32;
        const size_t obase = (size_t)b * Tt * Vv + (size_t)t * Vv + n0 + v0;
#pragma unroll 8
        for (int i = 0; i < 32; i++) out[obase + i] = red[(v0 + i) * 65 + b];
    }

    if (tid < Bsz) {
        const int b = tid;
        float bb = -3.4e38f;
        int   bi = 0x7fffffff;
#pragma unroll 8
        for (int r = 0; r < VT; r++) {
            float v2 = red[r * 65 + b];
            int   iv = n0 + r;
            if (v2 > bb || (v2 == bb && iv < bi)) { bb = v2; bi = iv; }
        }
        g_pval[b][blockIdx.x] = bb;
        g_pidx[b][blockIdx.x] = bi;
    }
    __syncthreads();

    // last-CTA final argmax
    if (tid == 0) {
        __threadfence();
        int old = atomicAdd(&g_cnt, 1);
        amLast = (old == NBLK_SCORE - 1);
    }
    __syncthreads();
    if (amLast) {
        __threadfence();
        if (tid < Bsz) {
            const int b = tid;
            float bv = -3.4e38f;
            int   bi = 0x7fffffff;
#pragma unroll 5
            for (int p = 0; p < NBLK_SCORE; p++) {
                float v = g_pval[b][p];
                int   i = g_pidx[b][p];
                if (v > bv || (v == bv && i < bi)) { bv = v; bi = i; }
            }
            g_xt[b] = bi;
            long long off = (long long)Bsz * Tt * Vv + (long long)b * Tt + t;
            if (off < (long long)out_size) out[off] = (float)bi;
        }
        if (tid == 0) g_cnt = 0;
    }
}

// ---------------- launch ----------------
extern "C" void kernel_launch(void* const* d_in, const int* in_sizes, int n_in,
                              void* d_out, int out_size) {
    const float* emb   = (const float*)d_in[0];
    const float* w_ih  = (const float*)d_in[1];
    const float* w_hh  = (const float*)d_in[2];
    const float* b_ih  = (const float*)d_in[3];
    const float* b_hh  = (const float*)d_in[4];
    const float* o2w   = (const float*)d_in[5];
    const float* o2b   = (const float*)d_in[6];
    const float* sw    = (const float*)d_in[7];
    const float* sb    = (const float*)d_in[8];
    float* out = (float*)d_out;
    (void)in_sizes; (void)n_in;

    cudaFuncSetAttribute(score_mma_kernel, cudaFuncAttributeMaxDynamicSharedMemorySize, DYN_BYTES);
    cudaFuncSetAttribute(lstm_mma_kernel, cudaFuncAttributeMaxDynamicSharedMemorySize, DYN_BYTES);

    init_kernel<<<512, 256>>>();
    split_w_kernel<<<2048, 256>>>(sw, emb);
    split_lstm_kernel<<<2048, 256>>>(w_ih, w_hh);
    for (int t = 0; t < Tt; t++) {
        lstm_mma_kernel<<<dim3(32, NSLICE_L), 256, DYN_BYTES>>>(0);
        lstm_cell_kernel<<<256, 256>>>(b_ih, b_hh, 0);
        lstm_mma_kernel<<<dim3(32, NSLICE_L), 256, DYN_BYTES>>>(1);
        lstm_cell_kernel<<<256, 256>>>(b_ih, b_hh, 1);
        o2emb_part_kernel<<<dim3(128, 2), 128>>>(o2w);
        o2emb_comb_kernel<<<256, 256>>>(o2b);
        score_mma_kernel<<<NBLK_SCORE, 256, DYN_BYTES>>>(sb, out, t, out_size);
    }
}

// round 14
// speedup vs baseline: 1.0118x; 1.0118x over previous
#include <cuda_runtime.h>
#include <cuda_fp16.h>
#include <math.h>
#include <stdint.h>

#define Bsz 64
#define Hd  1024
#define Ed  1024
#define Vv  32000
#define Ll  2
#define Tt  64
#define START_TOK 1

#define BK 32
#define XPAD 34
#define VT 128                        // rows per MMA tile
#define NBLK_SCORE (Vv / VT)          // 250
#define KC 64                         // fp16 K elems per chunk (128B rows)
#define NCH 16                        // score K chunks (1024/64)
#define NCH_L 4                       // lstm chunks per slice (256/64)
#define NSLICE_L 8                    // lstm K-split
#define A_PART 16384                  // 128 rows * 128B (one fp16 part)
#define B_PART 8192                   // 64 rows * 128B
#define A_REGION (2 * A_PART)         // 32768
#define B_REGION (2 * B_PART)         // 16384
#define STAGE_BYTES (A_REGION + B_REGION)  // 49152
#define DYN_BYTES (2 * STAGE_BYTES + 1024)  // 2-stage, ~99KB -> 2 CTAs/SM

typedef unsigned long long ull;

// ---------------- persistent device state ----------------
__device__ float  g_cbuf[Ll][Bsz][Hd];
__device__ float  g_hfp[Ll][Bsz][Hd];
__device__ int    g_xt[Bsz];
__device__ float  g_pval[Bsz][NBLK_SCORE];
__device__ int    g_pidx[Bsz][NBLK_SCORE];
__device__ float  g_gpart[NSLICE_L][Bsz][4 * Hd];
__device__ float  g_opart[2][Bsz][Ed];
__device__ int    g_cnt;

// pre-swizzled fp16x2 buffers (bulk-copy sources)
// g_wS:  [250 tiles][16 chunks][2 parts][128 rows x 128B swizzled]
__device__ __align__(128) unsigned char g_wS[(size_t)NBLK_SCORE * NCH * A_REGION];
// g_lwS: [layer*2+m][32 ntiles][16 chunks][2 parts][128 x 128B swizzled]
__device__ __align__(128) unsigned char g_lwS[(size_t)Ll * 2 * 32 * 16 * A_REGION];
// per-step B operands: [16 chunks][2 parts][64 rows x 128B swizzled]
__device__ __align__(128) unsigned char g_xS[NCH * B_REGION];          // emb gather
__device__ __align__(128) unsigned char g_hS[Ll][NCH * B_REGION];      // h splits
__device__ __align__(128) unsigned char g_oS[NCH * B_REGION];          // hid splits

// ---------------- helpers ----------------
__device__ __forceinline__ void ffma2(ull &acc, ull a, ull b) {
    asm("fma.rn.f32x2 %0, %1, %2, %0;" : "+l"(acc) : "l"(a), "l"(b));
}
__device__ __forceinline__ float fsum2(ull v) {
    return __uint_as_float((unsigned)v) + __uint_as_float((unsigned)(v >> 32));
}
__device__ __forceinline__ float sigmoidf_(float x) { return 1.0f / (1.0f + expf(-x)); }

__device__ __forceinline__ uint32_t smem_u32(const void* p) {
    uint32_t a;
    asm("{ .reg .u64 t; cvta.to.shared.u64 t, %1; cvt.u32.u64 %0, t; }" : "=r"(a) : "l"(p));
    return a;
}
__device__ __forceinline__ void ldsm_x4(uint32_t* r, uint32_t addr) {
    asm volatile("ldmatrix.sync.aligned.m8n8.x4.shared.b16 {%0,%1,%2,%3}, [%4];"
                 : "=r"(r[0]), "=r"(r[1]), "=r"(r[2]), "=r"(r[3]) : "r"(addr));
}
__device__ __forceinline__ void mma_f16(float* d, const uint32_t* a, uint32_t b0, uint32_t b1) {
    asm volatile(
        "mma.sync.aligned.m16n8k16.row.col.f32.f16.f16.f32 "
        "{%0,%1,%2,%3}, {%4,%5,%6,%7}, {%8,%9}, {%0,%1,%2,%3};"
        : "+f"(d[0]), "+f"(d[1]), "+f"(d[2]), "+f"(d[3])
        : "r"(a[0]), "r"(a[1]), "r"(a[2]), "r"(a[3]), "r"(b0), "r"(b1));
}
__device__ __forceinline__ uint32_t swz(uint32_t off) { return off ^ ((off >> 3) & 0x70); }

// bulk copy + mbarrier (baseline sm_90 PTX)
__device__ __forceinline__ void cpbulk(uint32_t dst, const void* src, uint32_t bytes, uint32_t mbar) {
    asm volatile("cp.async.bulk.shared::cluster.global.mbarrier::complete_tx::bytes [%0], [%1], %2, [%3];"
                 :: "r"(dst), "l"(src), "r"(bytes), "r"(mbar) : "memory");
}
__device__ __forceinline__ void mbar_init(uint32_t mb, uint32_t cnt) {
    asm volatile("mbarrier.init.shared.b64 [%0], %1;" :: "r"(mb), "r"(cnt) : "memory");
}
__device__ __forceinline__ void mbar_expect(uint32_t mb, uint32_t bytes) {
    asm volatile("mbarrier.arrive.expect_tx.shared.b64 _, [%0], %1;" :: "r"(mb), "r"(bytes) : "memory");
}
__device__ __forceinline__ void mbar_wait(uint32_t mbar, uint32_t parity) {
    asm volatile(
        "{\n\t.reg .pred P1;\n\t"
        "WAIT_LOOP_%=:\n\t"
        "mbarrier.try_wait.parity.acquire.cta.shared::cta.b64 P1, [%0], %1, 0x989680;\n\t"
        "@P1 bra.uni WAIT_DONE_%=;\n\t"
        "bra.uni WAIT_LOOP_%=;\n\t"
        "WAIT_DONE_%=:\n\t}"
        :: "r"(mbar), "r"(parity) : "memory");
}

__device__ __forceinline__ void split8(const float* s, __half* h0, __half* h1) {
#pragma unroll
    for (int i = 0; i < 8; i++) {
        float w = s[i];
        __half a = __float2half_rn(w);
        h0[i] = a;
        h1[i] = __float2half_rn(w - __half2float(a));
    }
}

// ---------------- init: zero c and h buffers, set start token ----------------
__global__ void init_kernel() {
    int idx = blockIdx.x * blockDim.x + threadIdx.x;   // 131072 total
    if (idx < Ll * Bsz * Hd) (&g_cbuf[0][0][0])[idx] = 0.0f;
    if (idx < (int)(sizeof(g_hS) / 4)) ((int*)g_hS)[idx] = 0;
    if (idx < Bsz) g_xt[idx] = START_TOK;
    if (idx == 0) g_cnt = 0;
}

// ---------------- one-time builds: pre-swizzled fp16x2 weight images ----------------
__global__ __launch_bounds__(256) void build_wS_kernel(const float* __restrict__ sw) {
    const size_t units = (size_t)Vv * Ed / 8;   // 4,096,000
    for (size_t u = blockIdx.x * 256ull + threadIdx.x; u < units; u += (size_t)gridDim.x * 256ull) {
        size_t v = u >> 7;
        int uu = (int)(u & 127);
        int ch = uu >> 3, cb = uu & 7;
        int tile = (int)(v >> 7), r = (int)(v & 127);
        __half h0[8], h1[8];
        split8(sw + v * Ed + ch * 64 + cb * 8, h0, h1);
        size_t base = ((size_t)tile * NCH + ch) * A_REGION;
        uint32_t so = swz((uint32_t)(r * 128 + cb * 16));
        *(uint4*)(g_wS + base + so)           = *(uint4*)h0;
        *(uint4*)(g_wS + base + A_PART + so)  = *(uint4*)h1;
    }
}
__global__ __launch_bounds__(256) void build_lwS_kernel(const float* __restrict__ w_ih,
                                                        const float* __restrict__ w_hh) {
    const size_t per_units = (size_t)4 * Hd * Hd / 8;   // 524288 per matrix
    const size_t units = per_units * Ll * 2;
    const size_t per = (size_t)4 * Hd * Hd;
    for (size_t u = blockIdx.x * 256ull + threadIdx.x; u < units; u += (size_t)gridDim.x * 256ull) {
        int mat = (int)(u / per_units);          // layer*2 + m
        size_t rem = u % per_units;
        size_t row = rem >> 7;
        int uu = (int)(rem & 127);
        int ch = uu >> 3, cb = uu & 7;
        int nt = (int)(row >> 7), r = (int)(row & 127);
        int layer = mat >> 1, m = mat & 1;
        const float* src = (m ? w_hh : w_ih) + (size_t)layer * per + row * Hd + ch * 64 + cb * 8;
        __half h0[8], h1[8];
        split8(src, h0, h1);
        size_t base = ((((size_t)mat * 32 + nt) * 16 + ch)) * A_REGION;
        uint32_t so = swz((uint32_t)(r * 128 + cb * 16));
        *(uint4*)(g_lwS + base + so)          = *(uint4*)h0;
        *(uint4*)(g_lwS + base + A_PART + so) = *(uint4*)h1;
    }
}

// ---------------- per-step: gather emb rows for current tokens (swizzled fp16x2) ----------------
__global__ __launch_bounds__(256) void embed_kernel(const float* __restrict__ emb) {
    int idx = blockIdx.x * 256 + threadIdx.x;   // 8192
    int r = idx >> 7;
    int uu = idx & 127;
    int ch = uu >> 3, cb = uu & 7;
    __half h0[8], h1[8];
    split8(emb + (size_t)g_xt[r] * Ed + ch * 64 + cb * 8, h0, h1);
    size_t base = (size_t)ch * B_REGION;
    uint32_t so = swz((uint32_t)(r * 128 + cb * 16));
    *(uint4*)(g_xS + base + so)          = *(uint4*)h0;
    *(uint4*)(g_xS + base + B_PART + so) = *(uint4*)h1;
}

// ---------------- LSTM partial GEMM: bulk loads + mma.sync fp16x2 ----------------
// grid = (32 gate-row tiles, 8 k-slices), 256 threads, 2-stage bulk pipeline.
__global__ __launch_bounds__(256, 2) void lstm_mma_kernel(int layer)
{
    extern __shared__ char dynsm[];
    __shared__ __align__(8) ull s_mb[2];

    const int tid  = threadIdx.x;
    const int wid  = tid >> 5;
    const int lane = tid & 31;
    const int n0   = blockIdx.x * VT;
    const int slice = blockIdx.y;
    const int m    = (slice >= 4) ? 1 : 0;

    const uint32_t dbase = (smem_u32(dynsm) + 1023u) & ~1023u;
    const uint32_t mbU   = smem_u32(&s_mb[0]);

    const unsigned char* abase = g_lwS + (((size_t)(layer * 2 + m) * 32 + blockIdx.x) * 16) * A_REGION;
    const unsigned char* bbase = (layer == 0)
        ? ((slice < 4) ? g_xS : g_hS[0])
        : ((slice < 4) ? g_hS[0] : g_hS[1]);

    if (tid == 0) { mbar_init(mbU, 1); mbar_init(mbU + 8, 1); }
    __syncthreads();

    auto issue = [&](int kc, int stg) {
        uint32_t mb = mbU + 8 * stg;
        uint32_t sb = dbase + stg * STAGE_BYTES;
        int gch = (slice & 3) * NCH_L + kc;
        mbar_expect(mb, STAGE_BYTES);
        cpbulk(sb,            abase + (size_t)gch * A_REGION, A_REGION, mb);
        cpbulk(sb + A_REGION, bbase + (size_t)gch * B_REGION, B_REGION, mb);
    };
    if (tid == 0) { issue(0, 0); issue(1, 1); }

    float acc[8][4];
#pragma unroll
    for (int j = 0; j < 8; j++)
#pragma unroll
        for (int q = 0; q < 4; q++) acc[j][q] = 0.0f;

    const int arow = 16 * wid + (lane & 15);
    const int asel = (lane >> 4) & 1;
    const int brow = ((lane & 16) ? 8 : 0) + (lane & 7);
    const int bsel = (lane >> 3) & 1;

    for (int c = 0; c < NCH_L; c++) {
        const int stg = c & 1;
        mbar_wait(mbU + 8 * stg, (c >> 1) & 1);

        const uint32_t sbase = dbase + stg * STAGE_BYTES;
        const uint32_t bb = sbase + A_REGION;
#pragma unroll
        for (int kk = 0; kk < 4; kk++) {
            const uint32_t aoff = swz((uint32_t)(arow * 128 + (kk * 2 + asel) * 16));
            uint32_t a0[4], a1[4];
            ldsm_x4(a0, sbase + 0 * A_PART + aoff);
            ldsm_x4(a1, sbase + 1 * A_PART + aoff);
#pragma unroll
            for (int jp = 0; jp < 4; jp++) {
                const uint32_t boff = swz((uint32_t)((jp * 16 + brow) * 128 + (kk * 2 + bsel) * 16));
                uint32_t b[4];
                ldsm_x4(b, bb + 0 * B_PART + boff);       // h0: (w0,h0),(w1,h0)
                mma_f16(acc[2 * jp + 0], a0, b[0], b[1]);
                mma_f16(acc[2 * jp + 1], a0, b[2], b[3]);
                mma_f16(acc[2 * jp + 0], a1, b[0], b[1]);
                mma_f16(acc[2 * jp + 1], a1, b[2], b[3]);
                ldsm_x4(b, bb + 1 * B_PART + boff);       // h1: (w0,h1)
                mma_f16(acc[2 * jp + 0], a0, b[0], b[1]);
                mma_f16(acc[2 * jp + 1], a0, b[2], b[3]);
            }
        }
        __syncthreads();
        if (tid == 0 && c + 2 < NCH_L) issue(c + 2, stg);
    }

    // epilogue: smem transpose -> coalesced partial writes
    float* red = (float*)(dynsm + (dbase - smem_u32(dynsm)));   // [128][65]
    const int r1 = 16 * wid + (lane >> 2);
    const int r2 = r1 + 8;
#pragma unroll
    for (int j = 0; j < 8; j++) {
        int cc = j * 8 + (lane & 3) * 2;
        red[r1 * 65 + cc + 0] = acc[j][0];
        red[r1 * 65 + cc + 1] = acc[j][1];
        red[r2 * 65 + cc + 0] = acc[j][2];
        red[r2 * 65 + cc + 1] = acc[j][3];
    }
    __syncthreads();
    {
        const int b  = tid >> 2;
        const int v0 = (tid & 3) * 32;
#pragma unroll 8
        for (int i = 0; i < 32; i++)
            g_gpart[slice][b][n0 + v0 + i] = red[(v0 + i) * 65 + b];
    }
}

// ---------------- LSTM cell: reduce partials + biases, nonlinearity, swizzled h split ----------------
__global__ __launch_bounds__(256) void lstm_cell_kernel(
    const float* __restrict__ b_ih_all, const float* __restrict__ b_hh_all, int layer)
{
    const int idx = blockIdx.x * 256 + threadIdx.x;   // 65536
    const int j   = idx & (Hd - 1);
    const int row = idx >> 10;

    float gi = b_ih_all[layer * 4 * Hd + 0 * Hd + j] + b_hh_all[layer * 4 * Hd + 0 * Hd + j];
    float gf = b_ih_all[layer * 4 * Hd + 1 * Hd + j] + b_hh_all[layer * 4 * Hd + 1 * Hd + j];
    float gg = b_ih_all[layer * 4 * Hd + 2 * Hd + j] + b_hh_all[layer * 4 * Hd + 2 * Hd + j];
    float go = b_ih_all[layer * 4 * Hd + 3 * Hd + j] + b_hh_all[layer * 4 * Hd + 3 * Hd + j];
#pragma unroll
    for (int s = 0; s < NSLICE_L; s++) {
        gi += g_gpart[s][row][0 * Hd + j];
        gf += g_gpart[s][row][1 * Hd + j];
        gg += g_gpart[s][row][2 * Hd + j];
        go += g_gpart[s][row][3 * Hd + j];
    }
    float cold = g_cbuf[layer][row][j];
    float cnew = sigmoidf_(gf) * cold + sigmoidf_(gi) * tanhf(gg);
    float hnew = sigmoidf_(go) * tanhf(cnew);
    g_cbuf[layer][row][j] = cnew;
    g_hfp[layer][row][j]  = hnew;

    __half h0 = __float2half_rn(hnew);
    __half h1 = __float2half_rn(hnew - __half2float(h0));
    int ch = j >> 6, cb = (j >> 3) & 7, w = j & 7;
    size_t off = (size_t)ch * B_REGION + swz((uint32_t)(row * 128 + cb * 16)) + w * 2;
    *(__half*)(g_hS[layer] + off)           = h0;
    *(__half*)(g_hS[layer] + off + B_PART)  = h1;
}

// ---------------- o2emb partial GEMM (scalar FFMA2, K-split x2) ----------------
__global__ __launch_bounds__(128) void o2emb_part_kernel(const float* __restrict__ o2w)
{
    __shared__ float xs[Bsz][XPAD];
    __shared__ float ws[8][XPAD];

    const int tid   = threadIdx.x;
    const int n0    = blockIdx.x * 8;
    const int slice = blockIdx.y;
    const int koff  = slice * 512;
    const int cg    = tid & 7;
    const int rg    = tid >> 3;
    const float* xsrc = &g_hfp[Ll - 1][0][0];

    ull acc[4];
#pragma unroll
    for (int i = 0; i < 4; i++) acc[i] = 0ULL;

    float4 px[4], pw;
    {
#pragma unroll
        for (int i = 0; i < 4; i++) {
            int item = tid + 128 * i;
            int r = item >> 3, c4 = item & 7;
            px[i] = *(const float4*)&xsrc[r * Hd + koff + 4 * c4];
        }
        if (tid < 64) {
            int c = tid >> 3, c4 = tid & 7;
            pw = *(const float4*)&o2w[(size_t)(n0 + c) * Hd + koff + 4 * c4];
        }
    }

    const int NCHU = 512 / BK;   // 16
    for (int chunk = 0; chunk < NCHU; chunk++) {
#pragma unroll
        for (int i = 0; i < 4; i++) {
            int item = tid + 128 * i;
            int r = item >> 3, c4 = item & 7;
            xs[r][4 * c4 + 0] = px[i].x; xs[r][4 * c4 + 1] = px[i].y;
            xs[r][4 * c4 + 2] = px[i].z; xs[r][4 * c4 + 3] = px[i].w;
        }
        if (tid < 64) {
            int c = tid >> 3, c4 = tid & 7;
            ws[c][4 * c4 + 0] = pw.x; ws[c][4 * c4 + 1] = pw.y;
            ws[c][4 * c4 + 2] = pw.z; ws[c][4 * c4 + 3] = pw.w;
        }
        __syncthreads();

        if (chunk + 1 < NCHU) {
            int k0 = koff + (chunk + 1) * BK;
#pragma unroll
            for (int i = 0; i < 4; i++) {
                int item = tid + 128 * i;
                int r = item >> 3, c4 = item & 7;
                px[i] = *(const float4*)&xsrc[r * Hd + k0 + 4 * c4];
            }
            if (tid < 64) {
                int c = tid >> 3, c4 = tid & 7;
                pw = *(const float4*)&o2w[(size_t)(n0 + c) * Hd + k0 + 4 * c4];
            }
        }

#pragma unroll
        for (int k2 = 0; k2 < BK / 2; k2++) {
            ull wv = *(const ull*)&ws[cg][2 * k2];
#pragma unroll
            for (int i = 0; i < 4; i++) {
                ull xv = *(const ull*)&xs[4 * rg + i][2 * k2];
                ffma2(acc[i], xv, wv);
            }
        }
        __syncthreads();
    }

    const int n = n0 + cg;
#pragma unroll
    for (int i = 0; i < 4; i++)
        g_opart[slice][4 * rg + i][n] = fsum2(acc[i]);
}

// ---------------- o2emb combine: bias + relu -> swizzled fp16x2 split ----------------
__global__ __launch_bounds__(256) void o2emb_comb_kernel(const float* __restrict__ o2b) {
    const int idx = blockIdx.x * 256 + threadIdx.x;   // 65536
    const int n   = idx & (Ed - 1);
    const int row = idx >> 10;
    float v = g_opart[0][row][n] + g_opart[1][row][n] + o2b[n];
    v = v > 0.0f ? v : 0.0f;
    __half p0 = __float2half_rn(v);
    __half p1 = __float2half_rn(v - __half2float(p0));
    int ch = n >> 6, cb = (n >> 3) & 7, w = n & 7;
    size_t off = (size_t)ch * B_REGION + swz((uint32_t)(row * 128 + cb * 16)) + w * 2;
    *(__half*)(g_oS + off)          = p0;
    *(__half*)(g_oS + off + B_PART) = p1;
}

// ---------------- score: bulk loads + mma.sync fp16x2 + fused final argmax ----------------
__global__ __launch_bounds__(256, 2) void score_mma_kernel(
    const float* __restrict__ score_b, float* __restrict__ out, int t, int out_size)
{
    extern __shared__ char dynsm[];
    __shared__ __align__(8) ull s_mb[2];
    __shared__ bool amLast;

    const int tid  = threadIdx.x;
    const int wid  = tid >> 5;
    const int lane = tid & 31;
    const int n0   = blockIdx.x * VT;

    const uint32_t dbase = (smem_u32(dynsm) + 1023u) & ~1023u;
    const uint32_t mbU   = smem_u32(&s_mb[0]);

    if (tid == 0) { mbar_init(mbU, 1); mbar_init(mbU + 8, 1); }
    __syncthreads();

    auto issue = [&](int kc, int stg) {
        uint32_t mb = mbU + 8 * stg;
        uint32_t sb = dbase + stg * STAGE_BYTES;
        mbar_expect(mb, STAGE_BYTES);
        cpbulk(sb,            g_wS + ((size_t)blockIdx.x * NCH + kc) * A_REGION, A_REGION, mb);
        cpbulk(sb + A_REGION, g_oS + (size_t)kc * B_REGION, B_REGION, mb);
    };
    if (tid == 0) { issue(0, 0); issue(1, 1); }

    float acc[8][4];
#pragma unroll
    for (int j = 0; j < 8; j++)
#pragma unroll
        for (int q = 0; q < 4; q++) acc[j][q] = 0.0f;

    const int arow = 16 * wid + (lane & 15);
    const int asel = (lane >> 4) & 1;
    const int brow = ((lane & 16) ? 8 : 0) + (lane & 7);
    const int bsel = (lane >> 3) & 1;

    for (int c = 0; c < NCH; c++) {
        const int stg = c & 1;
        mbar_wait(mbU + 8 * stg, (c >> 1) & 1);

        const uint32_t sbase = dbase + stg * STAGE_BYTES;
        const uint32_t bb = sbase + A_REGION;
#pragma unroll
        for (int kk = 0; kk < 4; kk++) {
            const uint32_t aoff = swz((uint32_t)(arow * 128 + (kk * 2 + asel) * 16));
            uint32_t a0[4], a1[4];
            ldsm_x4(a0, sbase + 0 * A_PART + aoff);
            ldsm_x4(a1, sbase + 1 * A_PART + aoff);
#pragma unroll
            for (int jp = 0; jp < 4; jp++) {
                const uint32_t boff = swz((uint32_t)((jp * 16 + brow) * 128 + (kk * 2 + bsel) * 16));
                uint32_t b[4];
                ldsm_x4(b, bb + 0 * B_PART + boff);
                mma_f16(acc[2 * jp + 0], a0, b[0], b[1]);
                mma_f16(acc[2 * jp + 1], a0, b[2], b[3]);
                mma_f16(acc[2 * jp + 0], a1, b[0], b[1]);
                mma_f16(acc[2 * jp + 1], a1, b[2], b[3]);
                ldsm_x4(b, bb + 1 * B_PART + boff);
                mma_f16(acc[2 * jp + 0], a0, b[0], b[1]);
                mma_f16(acc[2 * jp + 1], a0, b[2], b[3]);
            }
        }
        __syncthreads();
        if (tid == 0 && c + 2 < NCH) issue(c + 2, stg);
    }

    // ---------------- epilogue ----------------
    float* red = (float*)(dynsm + (dbase - smem_u32(dynsm)));  // [128][65]

    const int r1 = 16 * wid + (lane >> 2);
    const int r2 = r1 + 8;
    const float bias1 = score_b[n0 + r1];
    const float bias2 = score_b[n0 + r2];
#pragma unroll
    for (int j = 0; j < 8; j++) {
        int cc = j * 8 + (lane & 3) * 2;
        red[r1 * 65 + cc + 0] = acc[j][0] + bias1;
        red[r1 * 65 + cc + 1] = acc[j][1] + bias1;
        red[r2 * 65 + cc + 0] = acc[j][2] + bias2;
        red[r2 * 65 + cc + 1] = acc[j][3] + bias2;
    }
    __syncthreads();

    {
        const int b  = tid >> 2;
        const int v0 = (tid & 3) * 32;
        const size_t obase = (size_t)b * Tt * Vv + (size_t)t * Vv + n0 + v0;
#pragma unroll 8
        for (int i = 0; i < 32; i++) out[obase + i] = red[(v0 + i) * 65 + b];
    }

    if (tid < Bsz) {
        const int b = tid;
        float bb = -3.4e38f;
        int   bi = 0x7fffffff;
#pragma unroll 8
        for (int r = 0; r < VT; r++) {
            float v2 = red[r * 65 + b];
            int   iv = n0 + r;
            if (v2 > bb || (v2 == bb && iv < bi)) { bb = v2; bi = iv; }
        }
        g_pval[b][blockIdx.x] = bb;
        g_pidx[b][blockIdx.x] = bi;
    }
    __syncthreads();

    // last-CTA final argmax
    if (tid == 0) {
        __threadfence();
        int old = atomicAdd(&g_cnt, 1);
        amLast = (old == NBLK_SCORE - 1);
    }
    __syncthreads();
    if (amLast) {
        __threadfence();
        if (tid < Bsz) {
            const int b = tid;
            float bv = -3.4e38f;
            int   bi = 0x7fffffff;
#pragma unroll 5
            for (int p = 0; p < NBLK_SCORE; p++) {
                float v = g_pval[b][p];
                int   i = g_pidx[b][p];
                if (v > bv || (v == bv && i < bi)) { bv = v; bi = i; }
            }
            g_xt[b] = bi;
            long long off = (long long)Bsz * Tt * Vv + (long long)b * Tt + t;
            if (off < (long long)out_size) out[off] = (float)bi;
        }
        if (tid == 0) g_cnt = 0;
    }
}

// ---------------- launch ----------------
extern "C" void kernel_launch(void* const* d_in, const int* in_sizes, int n_in,
                              void* d_out, int out_size) {
    const float* emb   = (const float*)d_in[0];
    const float* w_ih  = (const float*)d_in[1];
    const float* w_hh  = (const float*)d_in[2];
    const float* b_ih  = (const float*)d_in[3];
    const float* b_hh  = (const float*)d_in[4];
    const float* o2w   = (const float*)d_in[5];
    const float* o2b   = (const float*)d_in[6];
    const float* sw    = (const float*)d_in[7];
    const float* sb    = (const float*)d_in[8];
    float* out = (float*)d_out;
    (void)in_sizes; (void)n_in;

    cudaFuncSetAttribute(score_mma_kernel, cudaFuncAttributeMaxDynamicSharedMemorySize, DYN_BYTES);
    cudaFuncSetAttribute(lstm_mma_kernel, cudaFuncAttributeMaxDynamicSharedMemorySize, DYN_BYTES);

    init_kernel<<<512, 256>>>();
    build_wS_kernel<<<2048, 256>>>(sw);
    build_lwS_kernel<<<2048, 256>>>(w_ih, w_hh);
    for (int t = 0; t < Tt; t++) {
        embed_kernel<<<32, 256>>>(emb);
        lstm_mma_kernel<<<dim3(32, NSLICE_L), 256, DYN_BYTES>>>(0);
        lstm_cell_kernel<<<256, 256>>>(b_ih, b_hh, 0);
        lstm_mma_kernel<<<dim3(32, NSLICE_L), 256, DYN_BYTES>>>(1);
        lstm_cell_kernel<<<256, 256>>>(b_ih, b_hh, 1);
        o2emb_part_kernel<<<dim3(128, 2), 128>>>(o2w);
        o2emb_comb_kernel<<<256, 256>>>(o2b);
        score_mma_kernel<<<NBLK_SCORE, 256, DYN_BYTES>>>(sb, out, t, out_size);
    }
}